// round 7
// baseline (speedup 1.0000x reference)
#include <cuda_runtime.h>
#include <cuda_bf16.h>
#include <math.h>

typedef unsigned int u32;

#define DOF   7
#define NB    5
#define KDIM  256
#define OUTC  42
#define RPB   64
#define BATCH 65536
#define GRID  (BATCH / RPB)   // 1024
#define TPB   256

// ---- smem layout (bytes). Swizzled 512 B row stride (no padding):
// off(r,kb) = r*512 + (((kb>>4) ^ (r&7))<<4) + (kb&15)   [kb = byte in row]
#define A_HI   0                    // 64 x 512 = 32768
#define A_LO   32768
#define B_HI   65536                // 48 x 512 = 24576
#define B_LO   90112
#define BIAS_B 114688               // 48 floats
#define SMEM_TOTAL 114944
// aliases after MMA:
#define CS     0                    // 4 x (64*50*4) = 51200 (over A tiles)
#define EB     65536                // 64*77*4 = 19712 (over B_HI)

// DMP linear map: y[t] = A[t] . [y0, g, u0..u4, 1]
__constant__ float c_A[11 * 8];

__device__ __forceinline__ u32 sm2u32(const void* p) {
    u32 a; asm("{.reg .u64 t; cvta.to.shared.u64 t,%1; cvt.u32.u64 %0,t;}"
               : "=r"(a) : "l"(p));
    return a;
}
__device__ __forceinline__ u32 swz(u32 r, u32 kb) {
    return r * 512u + ((((kb >> 4) ^ (r & 7u)) << 4) | (kb & 15u));
}
__device__ __forceinline__ void ldsm4(u32 addr, u32& r0, u32& r1, u32& r2, u32& r3) {
    asm volatile("ldmatrix.sync.aligned.m8n8.x4.shared.b16 {%0,%1,%2,%3},[%4];"
                 : "=r"(r0), "=r"(r1), "=r"(r2), "=r"(r3) : "r"(addr));
}
__device__ __forceinline__ void mma16816(float* c, const u32* a, u32 b0, u32 b1) {
    asm volatile(
        "mma.sync.aligned.m16n8k16.row.col.f32.bf16.bf16.f32 "
        "{%0,%1,%2,%3},{%4,%5,%6,%7},{%8,%9},{%0,%1,%2,%3};"
        : "+f"(c[0]), "+f"(c[1]), "+f"(c[2]), "+f"(c[3])
        : "r"(a[0]), "r"(a[1]), "r"(a[2]), "r"(a[3]), "r"(b0), "r"(b1));
}

__global__ __launch_bounds__(TPB, 2)
void fused_kernel(const float* __restrict__ x, const float* __restrict__ state,
                  const float* __restrict__ W, const float* __restrict__ bias,
                  float* __restrict__ out)
{
    extern __shared__ __align__(1024) char sm[];
    const u32 smb = sm2u32(sm);
    const int tid = threadIdx.x;
    const int wid = tid >> 5;
    const int lane = tid & 31;
    float* biass = (float*)(sm + BIAS_B);

    // ---- x -> bf16 hi/lo into swizzled A tiles (issue LDG first) ----
    const float4* xsrc = (const float4*)(x + (size_t)blockIdx.x * RPB * KDIM);
    #pragma unroll 4
    for (int j = 0; j < (RPB * KDIM / 4) / TPB; j++) {      // 16 iters
        int idx = tid + j * TPB;
        int r = idx >> 6;                  // row (64 float4 per row)
        int k4 = idx & 63;                 // float4 index -> kb = k4*8
        float4 v = __ldg(xsrc + idx);
        u32 ux = __float_as_uint(v.x), uy = __float_as_uint(v.y);
        u32 uz = __float_as_uint(v.z), uw2 = __float_as_uint(v.w);
        u32 hi01 = __byte_perm(ux, uy, 0x7632);
        u32 hi23 = __byte_perm(uz, uw2, 0x7632);
        float lx = v.x - __uint_as_float(ux & 0xFFFF0000u);
        float ly = v.y - __uint_as_float(uy & 0xFFFF0000u);
        float lz = v.z - __uint_as_float(uz & 0xFFFF0000u);
        float lw2 = v.w - __uint_as_float(uw2 & 0xFFFF0000u);
        u32 lo01, lo23;
        asm("cvt.rn.bf16x2.f32 %0,%1,%2;" : "=r"(lo01) : "f"(ly), "f"(lx));
        asm("cvt.rn.bf16x2.f32 %0,%1,%2;" : "=r"(lo23) : "f"(lw2), "f"(lz));
        u32 off = swz((u32)r, (u32)k4 * 8u);
        *(uint2*)(sm + A_HI + off) = make_uint2(hi01, hi23);
        *(uint2*)(sm + A_LO + off) = make_uint2(lo01, lo23);
    }

    // ---- stage bias; zero B pad rows 42..47 (raw range: swizzle is in-row) ----
    if (tid < 48) biass[tid] = (tid < OUTC) ? __ldg(bias + tid) : 0.0f;
    for (int i = tid; i < (6 * 512) / 4; i += TPB) {
        *(u32*)(sm + B_HI + 42 * 512 + 4 * i) = 0;
        *(u32*)(sm + B_LO + 42 * 512 + 4 * i) = 0;
    }

    // ---- W -> bf16 hi/lo, transposed into swizzled B tiles ----
    for (int i = tid; i < KDIM * OUTC; i += TPB) {
        int k = i / OUTC, n = i - k * OUTC;
        float w = __ldg(W + i);
        u32 uw = __float_as_uint(w);
        float hw = __uint_as_float(uw & 0xFFFF0000u);
        __nv_bfloat16 lw = __float2bfloat16(w - hw);
        u32 off = swz((u32)n, (u32)k * 2u);
        *(unsigned short*)(sm + B_HI + off) = (unsigned short)(uw >> 16);
        *(unsigned short*)(sm + B_LO + off) = *(const unsigned short*)&lw;
    }
    __syncthreads();

    // ---- MMA: 8 warps = 2 m-tiles(32 rows) x 4 k-quarters; 3 passes ----
    const int mw = wid & 1;            // m-tile: rows mw*32..+31
    const int kq = wid >> 1;           // k-quarter: 4 k16-steps

    float c[2][6][4];
    #pragma unroll
    for (int s2 = 0; s2 < 2; s2++)
        #pragma unroll
        for (int n = 0; n < 6; n++)
            #pragma unroll
            for (int q = 0; q < 4; q++) c[s2][n][q] = 0.0f;

    const u32 arow = (u32)(mw * 32) + (u32)(lane & 15);
    const u32 acolL = (u32)(lane >> 4);
    const u32 brow = (u32)((lane & 7) | ((lane >> 4) << 3));
    const u32 bcolL = (u32)((lane >> 3) & 1);

    #pragma unroll
    for (int s = 0; s < 4; s++) {
        u32 cb = (u32)(kq * 4 + s) * 2u;     // col16 base for this k16 step
        u32 ah[2][4], al[2][4], bh[12], bl[12];
        #pragma unroll
        for (int sub = 0; sub < 2; sub++) {
            u32 r = arow + (u32)sub * 16u;
            u32 ad = smb + swz(r, (cb + acolL) << 4);
            ldsm4(A_HI + ad, ah[sub][0], ah[sub][1], ah[sub][2], ah[sub][3]);
            ldsm4(A_LO + ad, al[sub][0], al[sub][1], al[sub][2], al[sub][3]);
        }
        #pragma unroll
        for (int nt = 0; nt < 3; nt++) {
            u32 r = brow + (u32)nt * 16u;
            u32 bd = smb + swz(r, (cb + bcolL) << 4);
            ldsm4(B_HI + bd, bh[nt*4], bh[nt*4+1], bh[nt*4+2], bh[nt*4+3]);
            ldsm4(B_LO + bd, bl[nt*4], bl[nt*4+1], bl[nt*4+2], bl[nt*4+3]);
        }
        #pragma unroll
        for (int sub = 0; sub < 2; sub++)
            #pragma unroll
            for (int n = 0; n < 6; n++) {
                int bi = (n >> 1) * 4 + (n & 1) * 2;
                mma16816(c[sub][n], ah[sub], bh[bi], bh[bi + 1]);  // hi*hi
                mma16816(c[sub][n], ah[sub], bl[bi], bl[bi + 1]);  // hi*lo
                mma16816(c[sub][n], al[sub], bh[bi], bh[bi + 1]);  // lo*hi
            }
    }
    __syncthreads();   // all tile reads done before aliases are written

    // ---- stage C partials: cs[kq][row][col], row stride 50 floats ----
    {
        float* cs = (float*)(sm + CS) + kq * (RPB * 50);
        int c0 = 2 * (lane & 3);
        #pragma unroll
        for (int sub = 0; sub < 2; sub++) {
            int r0 = mw * 32 + sub * 16 + (lane >> 2);
            #pragma unroll
            for (int n = 0; n < 6; n++) {
                int col = n * 8 + c0;
                *(float2*)&cs[r0 * 50 + col]       = make_float2(c[sub][n][0], c[sub][n][1]);
                *(float2*)&cs[(r0 + 8) * 50 + col] = make_float2(c[sub][n][2], c[sub][n][3]);
            }
        }
    }
    __syncthreads();

    // ---- epilogue: linear DMP map, one thread per batch row ----
    if (tid < RPB) {
        const float* cs = (const float*)(sm + CS) + tid * 50;
        float* eb = (float*)(sm + EB) + tid * 77;
        const float* st = state + ((size_t)(blockIdx.x * RPB + tid)) * DOF;

        float g[DOF], y0v[DOF], ku[DOF], wv[DOF][NB];
        #pragma unroll
        for (int d = 0; d < DOF; d++) {
            y0v[d] = __ldg(st + d);
            g[d] = cs[d] + cs[RPB*50 + d] + cs[2*RPB*50 + d] + cs[3*RPB*50 + d]
                 + biass[d];
            ku[d] = g[d] - y0v[d];
            #pragma unroll
            for (int j = 0; j < NB; j++) {
                int col = DOF + 5 * d + j;
                wv[d][j] = cs[col] + cs[RPB*50 + col] + cs[2*RPB*50 + col]
                         + cs[3*RPB*50 + col] + biass[col];
            }
            eb[d] = y0v[d];                 // t = 0
        }
        #pragma unroll
        for (int t = 1; t <= 10; t++) {
            float a0 = c_A[t*8+0], a1 = c_A[t*8+1], a2 = c_A[t*8+2], a3 = c_A[t*8+3];
            float a4 = c_A[t*8+4], a5 = c_A[t*8+5], a6 = c_A[t*8+6], a7 = c_A[t*8+7];
            #pragma unroll
            for (int d = 0; d < DOF; d++) {
                float v = a2 * wv[d][0];
                v = fmaf(a3, wv[d][1], v);
                v = fmaf(a4, wv[d][2], v);
                v = fmaf(a5, wv[d][3], v);
                v = fmaf(a6, wv[d][4], v);
                float yv = fmaf(a0, y0v[d], a7);
                yv = fmaf(a1, g[d], yv);
                yv = fmaf(v, ku[d], yv);
                eb[t * 7 + d] = yv;
            }
        }
    }
    __syncthreads();

    // ---- coalesced output copy: 64*77 floats = 1232 float4 ----
    const float4* s4 = (const float4*)(sm + EB);
    float4* d4 = (float4*)(out + (size_t)blockIdx.x * RPB * 77);
    #pragma unroll 1
    for (int i = tid; i < (RPB * 77) / 4; i += TPB) d4[i] = s4[i];
}

// ---------------------------------------------------------------------------
// Host: DMP linear map A (8 basis runs of the exact fp32 recursion).
// ---------------------------------------------------------------------------
static float hA[11 * 8];

static void compute_A_host() {
    float c[NB], s2[NB], P[100][NB];
    const float n15 = 11.180339887498949f;     // 5^1.5
    for (int j = 0; j < NB; j++) { c[j] = expf(-0.25f * j); s2[j] = n15 / c[j]; }
    float xv = 1.0f;
    for (int s = 0; s < 100; s++) {
        xv = xv - xv * 0.01f;
        float sum = 0.0f, psi[NB];
        for (int j = 0; j < NB; j++) {
            float d = xv - c[j];
            psi[j] = expf(-0.5f * d * d / s2[j]);
            sum += psi[j];
        }
        for (int j = 0; j < NB; j++) P[s][j] = psi[j] * xv / sum;
    }
    for (int b = 0; b < 8; b++) {              // basis: y0, g, u0..u4, const
        float y = (b == 0) ? 1.0f : 0.0f;
        float gb = (b == 1) ? 1.0f : 0.0f;
        float u[NB];
        for (int j = 0; j < NB; j++) u[j] = (b == 2 + j) ? 1.0f : 0.0f;
        float z = (b == 7) ? 0.05f : 0.0f;
        hA[0 * 8 + b] = y;
        int s = 0;
        for (int tt = 1; tt <= 10; tt++) {
            for (int ss = 0; ss < 10; ss++, s++) {
                float fx = 0.0f;
                for (int j = 0; j < NB; j++) fx += P[s][j] * u[j];
                float dz = 56.25f * (gb - y) - 15.0f * z + fx;
                y = y + z * 0.01f;             // uses old z
                z = z + dz * 0.01f;
            }
            hA[tt * 8 + b] = y;
        }
    }
}

extern "C" void kernel_launch(void* const* d_in, const int* in_sizes, int n_in,
                              void* d_out, int out_size)
{
    const float* x     = (const float*)d_in[0];
    const float* state = (const float*)d_in[1];
    const float* W     = (const float*)d_in[2];
    const float* b     = (const float*)d_in[3];
    float* out = (float*)d_out;

    compute_A_host();
    cudaMemcpyToSymbolAsync(c_A, hA, sizeof(hA), 0, cudaMemcpyHostToDevice);

    cudaFuncSetAttribute(fused_kernel,
                         cudaFuncAttributeMaxDynamicSharedMemorySize, SMEM_TOTAL);
    fused_kernel<<<GRID, TPB, SMEM_TOTAL>>>(x, state, W, b, out);
}

// round 8
// speedup vs baseline: 1.1108x; 1.1108x over previous
#include <cuda_runtime.h>
#include <cuda_bf16.h>
#include <math.h>

typedef unsigned int u32;

#define DOF   7
#define NB    5
#define KDIM  256
#define OUTC  42
#define RPB   128
#define BATCH 65536
#define GRID  (BATCH / RPB)   // 512
#define TPB   512

// ---- smem layout (bytes). Padded row stride 528 B (conflict-free, no swizzle ALU)
#define AST    528
#define A_HI   0                    // 128 x 528 = 67584
#define A_LO   67584
#define B_HI   135168               // 48 x 528 = 25344
#define B_LO   160512
#define BIAS_B 185856               // 48 floats
#define SMEM_TOTAL 186112
// aliases after MMA:
#define CS     0                    // 4 x (128*50*4) = 102400 (over A tiles)
#define EB     135168               // 128*77*4 = 39424 (over B tiles)

// Pre-converted W tiles (padded layout, ready for straight smem copy)
__device__ __align__(16) unsigned short g_Bhi[48 * 264];
__device__ __align__(16) unsigned short g_Blo[48 * 264];
__device__ __align__(16) float g_bias48[48];

// DMP linear map: y[t] = A[t] . [y0, g, u0..u4, 1]
__constant__ float c_A[11 * 8];

__device__ __forceinline__ u32 sm2u32(const void* p) {
    u32 a; asm("{.reg .u64 t; cvta.to.shared.u64 t,%1; cvt.u32.u64 %0,t;}"
               : "=r"(a) : "l"(p));
    return a;
}
__device__ __forceinline__ void ldsm4(u32 addr, u32& r0, u32& r1, u32& r2, u32& r3) {
    asm volatile("ldmatrix.sync.aligned.m8n8.x4.shared.b16 {%0,%1,%2,%3},[%4];"
                 : "=r"(r0), "=r"(r1), "=r"(r2), "=r"(r3) : "r"(addr));
}
__device__ __forceinline__ void mma16816(float* c, const u32* a, u32 b0, u32 b1) {
    asm volatile(
        "mma.sync.aligned.m16n8k16.row.col.f32.bf16.bf16.f32 "
        "{%0,%1,%2,%3},{%4,%5,%6,%7},{%8,%9},{%0,%1,%2,%3};"
        : "+f"(c[0]), "+f"(c[1]), "+f"(c[2]), "+f"(c[3])
        : "r"(a[0]), "r"(a[1]), "r"(a[2]), "r"(a[3]), "r"(b0), "r"(b1));
}

// ---------------------------------------------------------------------------
// Prep: W -> bf16 hi/lo tiles in padded [n][k] layout (+ bias), once.
// ---------------------------------------------------------------------------
__global__ void prep_kernel(const float* __restrict__ W,
                            const float* __restrict__ bias)
{
    int gid = blockIdx.x * 256 + threadIdx.x;   // 48 blocks x 256
    int n = gid >> 8, k = gid & 255;
    unsigned short hi = 0, lo = 0;
    if (n < OUTC) {
        float w = __ldg(W + k * OUTC + n);
        u32 uw = __float_as_uint(w);
        float hw = __uint_as_float(uw & 0xFFFF0000u);
        __nv_bfloat16 lb = __float2bfloat16(w - hw);
        hi = (unsigned short)(uw >> 16);
        lo = *(const unsigned short*)&lb;
    }
    g_Bhi[n * 264 + k] = hi;
    g_Blo[n * 264 + k] = lo;
    if (gid < 48) g_bias48[gid] = (gid < OUTC) ? __ldg(bias + gid) : 0.0f;
}

// ---------------------------------------------------------------------------
__global__ __launch_bounds__(TPB, 1)
void fused_kernel(const float* __restrict__ x, const float* __restrict__ state,
                  float* __restrict__ out)
{
    extern __shared__ __align__(1024) char sm[];
    const u32 smb = sm2u32(sm);
    const int tid = threadIdx.x;
    const int wid = tid >> 5;
    const int lane = tid & 31;
    float* biass = (float*)(sm + BIAS_B);

    // ---- x -> bf16 hi/lo, row-major A[r][k] ----
    const float4* xsrc = (const float4*)(x + (size_t)blockIdx.x * RPB * KDIM);
    #pragma unroll 4
    for (int j = 0; j < (RPB * KDIM / 4) / TPB; j++) {      // 16 iters
        int idx = tid + j * TPB;
        int r = idx >> 6, k4 = idx & 63;
        float4 v = __ldg(xsrc + idx);
        u32 ux = __float_as_uint(v.x), uy = __float_as_uint(v.y);
        u32 uz = __float_as_uint(v.z), uw2 = __float_as_uint(v.w);
        u32 hi01 = __byte_perm(ux, uy, 0x7632);
        u32 hi23 = __byte_perm(uz, uw2, 0x7632);
        float lx = v.x - __uint_as_float(ux & 0xFFFF0000u);
        float ly = v.y - __uint_as_float(uy & 0xFFFF0000u);
        float lz = v.z - __uint_as_float(uz & 0xFFFF0000u);
        float lw2 = v.w - __uint_as_float(uw2 & 0xFFFF0000u);
        u32 lo01, lo23;
        asm("cvt.rn.bf16x2.f32 %0,%1,%2;" : "=r"(lo01) : "f"(ly), "f"(lx));
        asm("cvt.rn.bf16x2.f32 %0,%1,%2;" : "=r"(lo23) : "f"(lw2), "f"(lz));
        u32 off = (u32)(r * AST + k4 * 8);
        *(uint2*)(sm + A_HI + off) = make_uint2(hi01, hi23);
        *(uint2*)(sm + A_LO + off) = make_uint2(lo01, lo23);
    }

    // ---- copy pre-converted W tiles (L2-hot, 16B vectors, conflict-free) ----
    {
        const uint4* sh = (const uint4*)g_Bhi;   // 1584 uint4
        const uint4* sl = (const uint4*)g_Blo;
        uint4* dh = (uint4*)(sm + B_HI);
        uint4* dl = (uint4*)(sm + B_LO);
        #pragma unroll
        for (int j = 0; j < 1584 / TPB + 1; j++) {
            int i = tid + j * TPB;
            if (i < 1584) { dh[i] = __ldg(sh + i); dl[i] = __ldg(sl + i); }
        }
        if (tid < 48) biass[tid] = g_bias48[tid];
    }
    __syncthreads();

    // ---- MMA: 16 warps = 4 m-tiles(32 rows) x 4 k-quarters; 3 passes ----
    const int mw = wid & 3;            // m-tile: rows mw*32..+31
    const int kq = wid >> 2;           // k-quarter: k16 steps kq*4..+3

    float c[2][6][4];
    #pragma unroll
    for (int s2 = 0; s2 < 2; s2++)
        #pragma unroll
        for (int n = 0; n < 6; n++)
            #pragma unroll
            for (int q = 0; q < 4; q++) c[s2][n][q] = 0.0f;

    const u32 arow = (u32)((mw * 32 + (lane & 15)) * AST + (lane >> 4) * 16);
    const u32 brow = (u32)((((lane & 7) | ((lane >> 4) << 3))) * AST
                           + ((lane >> 3) & 1) * 16);
    const u32 aHi = smb + A_HI + arow;
    const u32 aLo = smb + A_LO + arow;
    const u32 bHi = smb + B_HI + brow;
    const u32 bLo = smb + B_LO + brow;

    #pragma unroll
    for (int s = 0; s < 4; s++) {
        u32 ko = (u32)(kq * 4 + s) * 32u;
        u32 ah[2][4], al[2][4], bh[12], bl[12];
        #pragma unroll
        for (int sub = 0; sub < 2; sub++) {
            u32 ro = (u32)sub * (16u * AST);
            ldsm4(aHi + ro + ko, ah[sub][0], ah[sub][1], ah[sub][2], ah[sub][3]);
            ldsm4(aLo + ro + ko, al[sub][0], al[sub][1], al[sub][2], al[sub][3]);
        }
        #pragma unroll
        for (int nt = 0; nt < 3; nt++) {
            u32 ro = (u32)nt * (16u * AST);
            ldsm4(bHi + ro + ko, bh[nt*4], bh[nt*4+1], bh[nt*4+2], bh[nt*4+3]);
            ldsm4(bLo + ro + ko, bl[nt*4], bl[nt*4+1], bl[nt*4+2], bl[nt*4+3]);
        }
        #pragma unroll
        for (int sub = 0; sub < 2; sub++)
            #pragma unroll
            for (int n = 0; n < 6; n++) {
                int bi = (n >> 1) * 4 + (n & 1) * 2;
                mma16816(c[sub][n], ah[sub], bh[bi], bh[bi + 1]);  // hi*hi
                mma16816(c[sub][n], ah[sub], bl[bi], bl[bi + 1]);  // hi*lo
                mma16816(c[sub][n], al[sub], bh[bi], bh[bi + 1]);  // lo*hi
            }
    }
    __syncthreads();   // tile reads done before aliases are written

    // ---- stage C partials: cs[kq][row][col], row stride 50 floats ----
    {
        float* cs = (float*)(sm + CS) + kq * (RPB * 50);
        int c0 = 2 * (lane & 3);
        #pragma unroll
        for (int sub = 0; sub < 2; sub++) {
            int r0 = mw * 32 + sub * 16 + (lane >> 2);
            #pragma unroll
            for (int n = 0; n < 6; n++) {
                int col = n * 8 + c0;
                *(float2*)&cs[r0 * 50 + col]       = make_float2(c[sub][n][0], c[sub][n][1]);
                *(float2*)&cs[(r0 + 8) * 50 + col] = make_float2(c[sub][n][2], c[sub][n][3]);
            }
        }
    }
    __syncthreads();

    // ---- epilogue: linear DMP map, one thread per batch row ----
    if (tid < RPB) {
        const float* cs = (const float*)(sm + CS) + tid * 50;
        float* eb = (float*)(sm + EB) + tid * 77;
        const float* st = state + ((size_t)(blockIdx.x * RPB + tid)) * DOF;

        float g[DOF], y0v[DOF], ku[DOF], wv[DOF][NB];
        #pragma unroll
        for (int d = 0; d < DOF; d++) {
            y0v[d] = __ldg(st + d);
            g[d] = cs[d] + cs[RPB*50 + d] + cs[2*RPB*50 + d] + cs[3*RPB*50 + d]
                 + biass[d];
            ku[d] = g[d] - y0v[d];
            #pragma unroll
            for (int j = 0; j < NB; j++) {
                int col = DOF + 5 * d + j;
                wv[d][j] = cs[col] + cs[RPB*50 + col] + cs[2*RPB*50 + col]
                         + cs[3*RPB*50 + col] + biass[col];
            }
            eb[d] = y0v[d];                 // t = 0
        }
        #pragma unroll
        for (int t = 1; t <= 10; t++) {
            float a0 = c_A[t*8+0], a1 = c_A[t*8+1], a2 = c_A[t*8+2], a3 = c_A[t*8+3];
            float a4 = c_A[t*8+4], a5 = c_A[t*8+5], a6 = c_A[t*8+6], a7 = c_A[t*8+7];
            #pragma unroll
            for (int d = 0; d < DOF; d++) {
                float v = a2 * wv[d][0];
                v = fmaf(a3, wv[d][1], v);
                v = fmaf(a4, wv[d][2], v);
                v = fmaf(a5, wv[d][3], v);
                v = fmaf(a6, wv[d][4], v);
                float yv = fmaf(a0, y0v[d], a7);
                yv = fmaf(a1, g[d], yv);
                yv = fmaf(v, ku[d], yv);
                eb[t * 7 + d] = yv;
            }
        }
    }
    __syncthreads();

    // ---- coalesced output copy: 128*77 floats = 2464 float4 ----
    const float4* s4 = (const float4*)(sm + EB);
    float4* d4 = (float4*)(out + (size_t)blockIdx.x * RPB * 77);
    #pragma unroll 1
    for (int i = tid; i < (RPB * 77) / 4; i += TPB) d4[i] = s4[i];
}

// ---------------------------------------------------------------------------
// Host: DMP linear map A (8 basis runs of the exact fp32 recursion).
// ---------------------------------------------------------------------------
static float hA[11 * 8];

static void compute_A_host() {
    float c[NB], s2[NB], P[100][NB];
    const float n15 = 11.180339887498949f;     // 5^1.5
    for (int j = 0; j < NB; j++) { c[j] = expf(-0.25f * j); s2[j] = n15 / c[j]; }
    float xv = 1.0f;
    for (int s = 0; s < 100; s++) {
        xv = xv - xv * 0.01f;
        float sum = 0.0f, psi[NB];
        for (int j = 0; j < NB; j++) {
            float d = xv - c[j];
            psi[j] = expf(-0.5f * d * d / s2[j]);
            sum += psi[j];
        }
        for (int j = 0; j < NB; j++) P[s][j] = psi[j] * xv / sum;
    }
    for (int b = 0; b < 8; b++) {              // basis: y0, g, u0..u4, const
        float y = (b == 0) ? 1.0f : 0.0f;
        float gb = (b == 1) ? 1.0f : 0.0f;
        float u[NB];
        for (int j = 0; j < NB; j++) u[j] = (b == 2 + j) ? 1.0f : 0.0f;
        float z = (b == 7) ? 0.05f : 0.0f;
        hA[0 * 8 + b] = y;
        int s = 0;
        for (int tt = 1; tt <= 10; tt++) {
            for (int ss = 0; ss < 10; ss++, s++) {
                float fx = 0.0f;
                for (int j = 0; j < NB; j++) fx += P[s][j] * u[j];
                float dz = 56.25f * (gb - y) - 15.0f * z + fx;
                y = y + z * 0.01f;             // uses old z
                z = z + dz * 0.01f;
            }
            hA[tt * 8 + b] = y;
        }
    }
}

extern "C" void kernel_launch(void* const* d_in, const int* in_sizes, int n_in,
                              void* d_out, int out_size)
{
    const float* x     = (const float*)d_in[0];
    const float* state = (const float*)d_in[1];
    const float* W     = (const float*)d_in[2];
    const float* b     = (const float*)d_in[3];
    float* out = (float*)d_out;

    compute_A_host();
    cudaMemcpyToSymbolAsync(c_A, hA, sizeof(hA), 0, cudaMemcpyHostToDevice);

    prep_kernel<<<48, 256>>>(W, b);
    cudaFuncSetAttribute(fused_kernel,
                         cudaFuncAttributeMaxDynamicSharedMemorySize, SMEM_TOTAL);
    fused_kernel<<<GRID, TPB, SMEM_TOTAL>>>(x, state, out);
}